// round 7
// baseline (speedup 1.0000x reference)
#include <cuda_runtime.h>
#include <math.h>

#define Bc 8
#define Cc 64
#define Nn 128
#define Tc 288
#define TP 300
#define PRED 12
#define ROWS (Bc*Cc*Nn)   // 65536

// ---------------- scratch (static device globals; no allocation) -------------
__device__ float g_x1[ROWS*TP];
__device__ float g_x2[ROWS*TP];
__device__ float g_x3[ROWS*TP];
__device__ float g_x4[ROWS*TP];
__device__ float g_ltm[ROWS];
__device__ float g_lts[ROWS];
__device__ float g_sm[ROWS*24];
__device__ float g_ss[ROWS*24];
__device__ float g_stm[ROWS*Tc];
__device__ float g_sts[ROWS*Tc];
__device__ float g_spm[ROWS*Tc];
__device__ float g_sps[ROWS*Tc];
__device__ float g_adj[Nn*Nn];
__device__ float g_wcomb[832*2*128];   // [ic][tap][oc(128: 64 conv1 | 64 conv2)]
__device__ float g_wrT[64*64];         // res_w transposed [c][o]
__device__ float g_wkT[64*64];         // skip_w transposed [c][o]
__device__ float g_tab[Bc*Nn*24*128];  // folded const+seasonal contribution [bn][ph][oc]
__device__ float g_corr[Bc*Nn*128];    // t==0 left-pad correction [bn][oc]

// ---------------- K0: adjacency softmax -------------------------------------
__global__ void k_adj(const float* __restrict__ emb){
    int n = blockIdx.x, m = threadIdx.x;
    float d = 0.f;
    #pragma unroll
    for (int k = 0; k < 64; k++) d += emb[n*64+k]*emb[m*64+k];
    if (m == n) d -= 10.f;
    __shared__ float red[4];
    int lane = m & 31, w = m >> 5;
    float v = d;
    #pragma unroll
    for (int o = 16; o > 0; o >>= 1) v = fmaxf(v, __shfl_xor_sync(0xffffffffu, v, o));
    if (lane == 0) red[w] = v;
    __syncthreads();
    float mx = fmaxf(fmaxf(red[0],red[1]), fmaxf(red[2],red[3]));
    __syncthreads();
    float e = expf(d - mx);
    v = e;
    #pragma unroll
    for (int o = 16; o > 0; o >>= 1) v += __shfl_xor_sync(0xffffffffu, v, o);
    if (lane == 0) red[w] = v;
    __syncthreads();
    float s = red[0]+red[1]+red[2]+red[3];
    g_adj[n*Nn + m] = e / s;
}

// ---------------- K_w: weight reorder ----------------------------------------
__global__ void k_wprep(const float* __restrict__ c1w, const float* __restrict__ c2w,
                        const float* __restrict__ resw, const float* __restrict__ skw){
    int i = blockIdx.x*256 + threadIdx.x;
    if (i < 832*2*128) {
        int oc = i & 127, tap = (i >> 7) & 1, ic = i >> 8;
        g_wcomb[i] = (oc < 64) ? c1w[(oc*832+ic)*2 + tap]
                               : c2w[((oc-64)*832+ic)*2 + tap];
    }
    if (i < 4096) {
        int o = i >> 6, c = i & 63;
        g_wrT[c*64+o] = resw[i];
        g_wkT[c*64+o] = skw[i];
    }
}

// ---------------- K1: per-row temporal norms ---------------------------------
__global__ void k_temporal(const float* __restrict__ x){
    int row = blockIdx.x;
    int t = threadIdx.x;                       // 0..287
    __shared__ float s1[Tc], s2[Tc];
    __shared__ float rs[9], rq[9];
    __shared__ float smv[24], siv[24];
    float xv = x[row*Tc + t];
    // long-term (whole-sequence) stats
    float sum = xv, sq = xv*xv;
    #pragma unroll
    for (int o = 16; o > 0; o >>= 1) {
        sum += __shfl_down_sync(0xffffffffu, sum, o);
        sq  += __shfl_down_sync(0xffffffffu, sq,  o);
    }
    if ((t & 31) == 0) { rs[t>>5] = sum; rq[t>>5] = sq; }
    __syncthreads();
    if (t == 0) {
        float a = 0.f, b = 0.f;
        #pragma unroll
        for (int i = 0; i < 9; i++) { a += rs[i]; b += rq[i]; }
        rs[0] = a; rq[0] = b;
    }
    __syncthreads();
    float m1 = rs[0] * (1.f/Tc);
    float v1 = rq[0] * (1.f/Tc) - m1*m1 + 1e-5f;
    float x1v = (xv - m1) * rsqrtf(v1 + 0.01f);
    s1[t] = x1v;
    g_x1[row*TP + t] = x1v;
    if (t == 0) { g_ltm[row] = m1; g_lts[row] = sqrtf(v1); }
    __syncthreads();
    // seasonal (cycle 24, 12 chunks)
    if (t < 24) {
        float a = 0.f, b = 0.f;
        #pragma unroll
        for (int k = 0; k < 12; k++) { float v = s1[t + 24*k]; a += v; b += v*v; }
        float mm = a * (1.f/12.f);
        float vv = b * (1.f/12.f) - mm*mm + 1e-5f;
        smv[t] = mm;
        siv[t] = rsqrtf(vv + 0.01f);
        g_sm[row*24 + t] = mm;
        g_ss[row*24 + t] = sqrtf(vv);
    }
    __syncthreads();
    int ph = t % 24;
    float x2v = (x1v - smv[ph]) * siv[ph];
    s2[t] = x2v;
    g_x2[row*TP + t] = x2v;
    __syncthreads();
    // short-period sliding window (width 12, window ends at max(t,11))
    int te = (t < 11) ? 11 : t;
    float a = 0.f, b = 0.f;
    #pragma unroll
    for (int j = 0; j < 12; j++) { float v = s2[te-11+j]; a += v; b += v*v; }
    float mm = a * (1.f/12.f);
    float vv = b * (1.f/12.f) - mm*mm + 1e-5f;
    g_stm[row*Tc + t] = mm;
    g_sts[row*Tc + t] = sqrtf(vv);
    g_x3[row*TP + t] = (x2v - mm) * rsqrtf(vv + 0.01f);
}

// ---------------- K2: spatial norm -------------------------------------------
__global__ void k_spatial(){
    int bc = blockIdx.x;            // 0..511 (b*64+c)
    int t0 = blockIdx.y * 32;
    __shared__ float s3[Nn*32], q3[Nn*32];
    int tid = threadIdx.x;          // 128
    for (int idx = tid; idx < Nn*32; idx += 128) {
        int m = idx >> 5, j = idx & 31;
        float v = g_x3[(bc*Nn + m)*TP + t0 + j];
        s3[idx] = v; q3[idx] = v*v;
    }
    __syncthreads();
    int lane = tid & 31, w = tid >> 5;
    int t = t0 + lane;
    for (int ni = 0; ni < 32; ni++) {
        int n = w*32 + ni;
        const float* ar = &g_adj[n*Nn];
        float a1 = 0.f, a2 = 0.f;
        #pragma unroll 8
        for (int m = 0; m < Nn; m++) {
            float a = ar[m];
            a1 = fmaf(a, s3[m*32+lane], a1);
            a2 = fmaf(a, q3[m*32+lane], a2);
        }
        float var = a2 - a1*a1 + 1e-5f;
        float xv = s3[n*32 + lane];
        int ro = bc*Nn + n;
        g_x4[ro*TP + t] = (xv - a1) * rsqrtf(var + 0.01f);
        g_spm[ro*Tc + t] = a1;
        g_sps[ro*Tc + t] = sqrtf(var);
    }
}

// ---------------- K3: residual extrapolation GEMMs ---------------------------
__global__ void __launch_bounds__(256) k_extrap(
        const float* __restrict__ w1, const float* __restrict__ b1,
        const float* __restrict__ w2, const float* __restrict__ b2,
        const float* __restrict__ w3, const float* __restrict__ b3,
        const float* __restrict__ w4, const float* __restrict__ b4){
    int which = blockIdx.z >> 3;
    int b = blockIdx.z & 7;
    int o0 = blockIdx.x * 64;
    int n0 = blockIdx.y * 32;
    const float* wt; const float* bs; float* xio;
    if (which == 0)      { wt = w1; bs = b1; xio = g_x1; }
    else if (which == 1) { wt = w2; bs = b2; xio = g_x2; }
    else if (which == 2) { wt = w3; bs = b3; xio = g_x3; }
    else                 { wt = w4; bs = b4; xio = g_x4; }

    __shared__ __align__(16) float Vs[64*32];
    __shared__ float Ws[64*64];
    int tid = threadIdx.x;
    int tx = tid & 7;          // 4 n each
    int ty = tid >> 3;         // o = o0+ty and o0+ty+32
    float acc0[4] = {0,0,0,0}, acc1[4] = {0,0,0,0};
    for (int kt = 0; kt < 12; kt++) {
        __syncthreads();
        for (int idx = tid; idx < 2048; idx += 256) {
            int k = idx >> 5, nn = idx & 31;
            int kk = kt*64 + k;
            int c = kk / 12, l = kk - c*12;
            Vs[idx] = xio[((b*Cc + c)*Nn + n0 + nn)*TP + 276 + l];
        }
        for (int idx = tid; idx < 4096; idx += 256) {
            int k = idx >> 6, oc = idx & 63;
            Ws[idx] = wt[(o0 + oc)*768 + kt*64 + k];
        }
        __syncthreads();
        #pragma unroll 8
        for (int k = 0; k < 64; k++) {
            float w0 = Ws[k*64 + ty];
            float wA = Ws[k*64 + 32 + ty];
            float4 vv = *(const float4*)&Vs[k*32 + tx*4];
            float v[4] = {vv.x, vv.y, vv.z, vv.w};
            #pragma unroll
            for (int j = 0; j < 4; j++) {
                acc0[j] = fmaf(w0, v[j], acc0[j]);
                acc1[j] = fmaf(wA, v[j], acc1[j]);
            }
        }
    }
    int o = o0 + ty;
    float bv = bs[o];
    int p = o >> 6, c2 = o & 63;
    #pragma unroll
    for (int j = 0; j < 4; j++)
        xio[((b*Cc + c2)*Nn + n0 + tx*4 + j)*TP + Tc + p] = acc0[j] + bv;
    o = o0 + ty + 32;
    bv = bs[o]; p = o >> 6; c2 = o & 63;
    #pragma unroll
    for (int j = 0; j < 4; j++)
        xio[((b*Cc + c2)*Nn + n0 + tx*4 + j)*TP + Tc + p] = acc1[j] + bv;
}

// ---------------- K_tab: fold constant + periodic xcat groups ----------------
// Contribution of xcat groups 2,3 (constant in t) and 5,6 (period-24) to the
// gated conv, as a per-(b,n) table over (phase=t%24, oc). corr corrects the
// t==0 left zero-pad (tap0 reads 0 instead of the periodic/constant value).
__global__ void __launch_bounds__(128) k_tab(){
    int bn = blockIdx.x;            // b*128 + n
    int b = bn >> 7, n = bn & 127;
    __shared__ float s_sm[64*24], s_ss[64*24], s_ltm[64], s_lts[64];
    int tid = threadIdx.x;
    for (int idx = tid; idx < 1536; idx += 128) {
        int c = idx / 24, ph = idx - c*24;
        int row = (b*Cc + c)*Nn + n;
        s_sm[idx] = g_sm[row*24 + ph];
        s_ss[idx] = g_ss[row*24 + ph];
    }
    if (tid < 64) {
        int row = (b*Cc + tid)*Nn + n;
        s_ltm[tid] = g_ltm[row];
        s_lts[tid] = g_lts[row];
    }
    __syncthreads();
    int oc = tid;                   // 0..127
    float tab[24];
    #pragma unroll
    for (int p = 0; p < 24; p++) tab[p] = 0.f;
    float corr = 0.f, base = 0.f;
    for (int c = 0; c < 64; c++) {
        float w2t0 = g_wcomb[((128+c)*2+0)*128+oc];
        float w2t1 = g_wcomb[((128+c)*2+1)*128+oc];
        float w3t0 = g_wcomb[((192+c)*2+0)*128+oc];
        float w3t1 = g_wcomb[((192+c)*2+1)*128+oc];
        base += (w2t0+w2t1)*s_ltm[c] + (w3t0+w3t1)*s_lts[c];
        corr += w2t0*s_ltm[c] + w3t0*s_lts[c];
        float w5t0 = g_wcomb[((320+c)*2+0)*128+oc];
        float w5t1 = g_wcomb[((320+c)*2+1)*128+oc];
        float w6t0 = g_wcomb[((384+c)*2+0)*128+oc];
        float w6t1 = g_wcomb[((384+c)*2+1)*128+oc];
        const float* smc = &s_sm[c*24];
        const float* ssc = &s_ss[c*24];
        corr += w5t0*smc[23] + w6t0*ssc[23];
        #pragma unroll
        for (int p = 0; p < 24; p++) {
            int pm = (p + 23) % 24;   // phase of t-1
            tab[p] = fmaf(w5t0, smc[pm], tab[p]);
            tab[p] = fmaf(w5t1, smc[p],  tab[p]);
            tab[p] = fmaf(w6t0, ssc[pm], tab[p]);
            tab[p] = fmaf(w6t1, ssc[p],  tab[p]);
        }
    }
    #pragma unroll
    for (int p = 0; p < 24; p++)
        g_tab[(bn*24 + p)*128 + oc] = tab[p] + base;
    g_corr[bn*128 + oc] = corr;
}

// ---------------- K4: fused gated conv + output 1x1s -------------------------
__device__ __forceinline__ float gather_xcat(const float* __restrict__ x,
                                             int b, int ch, int n, int t){
    int g = ch >> 6, c = ch & 63;
    int row = (b*Cc + c)*Nn + n;
    int tc = (t < Tc) ? t : (Tc - 1);
    switch (g) {
        case 0:  return x[row*Tc + tc];
        case 1:  return g_x1[row*TP + t];
        case 4:  return g_x2[row*TP + t];
        case 7:  return g_x3[row*TP + t];
        case 8:  return g_stm[row*Tc + tc];
        case 9:  return g_sts[row*Tc + tc];
        case 10: return g_x4[row*TP + t];
        case 11: return g_spm[row*Tc + tc];
        default: return g_sps[row*Tc + tc];   // 12
    }
}

__global__ void __launch_bounds__(256) k_convout(const float* __restrict__ x,
        const float* __restrict__ c1b, const float* __restrict__ c2b,
        const float* __restrict__ resb, const float* __restrict__ skb,
        float* __restrict__ out){
    int t0 = blockIdx.x * 64;
    int n  = blockIdx.y;
    int b  = blockIdx.z;
    int bn = b*Nn + n;
    __shared__ float xs[16*68];
    __shared__ __align__(16) float wz[64*68];   // weights (4096 floats) in loop, z (4352) after
    __shared__ float tabs[24*128];
    __shared__ float corrs[128];
    int tid = threadIdx.x;
    for (int idx = tid; idx < 3072; idx += 256) tabs[idx] = g_tab[bn*3072 + idx];
    if (tid < 128) corrs[tid] = g_corr[bn*128 + tid];
    int ocg = tid & 15;   // c base = ocg*4
    int tg  = tid >> 4;   // t base = tg*4
    float acc1[4][4] = {}, acc2[4][4] = {};
    for (int kti = 0; kti < 36; kti++) {
        // skip kt in {8..15} (const groups 2,3) and {20..27} (seasonal 5,6)
        int kt = (kti < 8) ? kti : ((kti < 12) ? kti + 8 : kti + 16);
        __syncthreads();
        for (int idx = tid; idx < 16*65; idx += 256) {
            int icl = idx / 65, j = idx - icl*65;
            int t = t0 - 1 + j;
            float v = 0.f;
            if (t >= 0 && t < TP) v = gather_xcat(x, b, kt*16 + icl, n, t);
            xs[icl*68 + j] = v;
        }
        for (int idx = tid; idx < 4096; idx += 256)
            wz[idx] = g_wcomb[kt*4096 + idx];
        __syncthreads();
        #pragma unroll
        for (int ic = 0; ic < 16; ic++) {
            float xv[5];
            #pragma unroll
            for (int r = 0; r < 5; r++) xv[r] = xs[ic*68 + tg*4 + r];
            #pragma unroll
            for (int tap = 0; tap < 2; tap++) {
                float4 wA = *(const float4*)&wz[(ic*2+tap)*128 + ocg*4];
                float4 wB = *(const float4*)&wz[(ic*2+tap)*128 + 64 + ocg*4];
                float wa[4] = {wA.x, wA.y, wA.z, wA.w};
                float wb[4] = {wB.x, wB.y, wB.z, wB.w};
                #pragma unroll
                for (int i = 0; i < 4; i++)
                    #pragma unroll
                    for (int j = 0; j < 4; j++) {
                        acc1[i][j] = fmaf(wa[i], xv[j+tap], acc1[i][j]);
                        acc2[i][j] = fmaf(wb[i], xv[j+tap], acc2[i][j]);
                    }
            }
        }
    }
    __syncthreads();   // done reading wz as weights
    // gating epilogue: z -> wz (reused as [c][t_local] with stride 68)
    #pragma unroll
    for (int i = 0; i < 4; i++) {
        int c = ocg*4 + i;
        float bb1 = c1b[c], bb2 = c2b[c];
        #pragma unroll
        for (int j = 0; j < 4; j++) {
            int lt = tg*4 + j;
            int t = t0 + lt;
            int ph = t % 24;
            float a1 = acc1[i][j] + tabs[ph*128 + c]      + bb1;
            float a2 = acc2[i][j] + tabs[ph*128 + 64 + c] + bb2;
            if (t == 0) { a1 -= corrs[c]; a2 -= corrs[64 + c]; }
            float zg = tanhf(a1) * (1.f / (1.f + expf(-a2)));
            wz[c*68 + lt] = zg;
        }
    }
    __syncthreads();
    // output 1x1 convs on z
    int tb = tg*4;
    const float* wsel = (t0 + tb >= Tc) ? g_wkT : g_wrT;
    float acc[4][4] = {};
    #pragma unroll 4
    for (int k = 0; k < 64; k++) {
        float4 zv = *(const float4*)&wz[k*68 + tb];
        float4 wv = *(const float4*)&wsel[k*64 + ocg*4];
        float z4[4] = {zv.x, zv.y, zv.z, zv.w};
        float w4[4] = {wv.x, wv.y, wv.z, wv.w};
        #pragma unroll
        for (int i = 0; i < 4; i++)
            #pragma unroll
            for (int j = 0; j < 4; j++)
                acc[i][j] = fmaf(w4[i], z4[j], acc[i][j]);
    }
    const size_t SZ1 = (size_t)Bc*Cc*Nn*Tc;
    #pragma unroll
    for (int i = 0; i < 4; i++) {
        int oc = ocg*4 + i;
        float br = resb[oc], bk = skb[oc];
        #pragma unroll
        for (int j = 0; j < 4; j++) {
            int t = t0 + tb + j;
            if (t < Tc)
                out[((size_t)(b*Cc + oc)*Nn + n)*Tc + t] = acc[i][j] + br;
            else if (t < TP)
                out[SZ1 + ((size_t)(b*Cc + oc)*Nn + n)*PRED + (t - Tc)] = acc[i][j] + bk;
        }
    }
}

// ---------------- launcher ----------------------------------------------------
extern "C" void kernel_launch(void* const* d_in, const int* in_sizes, int n_in,
                              void* d_out, int out_size){
    const float* x    = (const float*)d_in[0];
    const float* emb  = (const float*)d_in[1];
    const float* re1w = (const float*)d_in[2];  const float* re1b = (const float*)d_in[3];
    const float* re2w = (const float*)d_in[4];  const float* re2b = (const float*)d_in[5];
    const float* re3w = (const float*)d_in[6];  const float* re3b = (const float*)d_in[7];
    const float* re4w = (const float*)d_in[8];  const float* re4b = (const float*)d_in[9];
    const float* c1w  = (const float*)d_in[10]; const float* c1b  = (const float*)d_in[11];
    const float* c2w  = (const float*)d_in[12]; const float* c2b  = (const float*)d_in[13];
    const float* skw  = (const float*)d_in[14]; const float* skb  = (const float*)d_in[15];
    const float* resw = (const float*)d_in[16]; const float* resb = (const float*)d_in[17];

    k_adj<<<128, 128>>>(emb);
    k_wprep<<<(832*2*128 + 255)/256, 256>>>(c1w, c2w, resw, skw);
    k_temporal<<<ROWS, Tc>>>(x);
    k_spatial<<<dim3(512, 9, 1), 128>>>();
    k_extrap<<<dim3(12, 4, 32), 256>>>(re1w, re1b, re2w, re2b, re3w, re3b, re4w, re4b);
    k_tab<<<Bc*Nn, 128>>>();
    k_convout<<<dim3(5, 128, 8), 256>>>(x, c1b, c2b, resb, skb, (float*)d_out);
}

// round 13
// speedup vs baseline: 1.3175x; 1.3175x over previous
#include <cuda_runtime.h>
#include <math.h>

#define Bc 8
#define Cc 64
#define Nn 128
#define Tc 288
#define TP 300
#define PRED 12
#define ROWS (Bc*Cc*Nn)   // 65536

// ---------------- f32x2 packed helpers (FFMA2 path, sm_100+) ------------------
__device__ __forceinline__ unsigned long long packdup(float v){
    unsigned long long r; asm("mov.b64 %0, {%1, %1};" : "=l"(r) : "f"(v)); return r;
}
__device__ __forceinline__ void fma2(unsigned long long &d, unsigned long long a,
                                     unsigned long long b){
    asm("fma.rn.f32x2 %0, %1, %2, %0;" : "+l"(d) : "l"(a), "l"(b));
}
__device__ __forceinline__ unsigned long long mul2(unsigned long long a,
                                                   unsigned long long b){
    unsigned long long r; asm("mul.rn.f32x2 %0, %1, %2;" : "=l"(r) : "l"(a), "l"(b));
    return r;
}
__device__ __forceinline__ void unpack2(unsigned long long v, float &lo, float &hi){
    asm("mov.b64 {%0, %1}, %2;" : "=f"(lo), "=f"(hi) : "l"(v));
}

// ---------------- scratch (static device globals; no allocation) -------------
__device__ float g_x1[ROWS*TP];
__device__ float g_x2[ROWS*TP];
__device__ float g_x3[ROWS*TP];
__device__ float g_x4[ROWS*TP];
__device__ float g_ltm[ROWS];
__device__ float g_lts[ROWS];
__device__ float g_sm[ROWS*24];
__device__ float g_ss[ROWS*24];
__device__ float g_stm[ROWS*Tc];
__device__ float g_sts[ROWS*Tc];
__device__ float g_spm[ROWS*Tc];
__device__ float g_sps[ROWS*Tc];
__device__ float g_adj[Nn*Nn];
__device__ __align__(16) float g_adjT[Nn*Nn];   // adjT[m][n] = adj[n][m]
__device__ float g_wcomb[832*2*128];   // [ic][tap][oc(128: 64 conv1 | 64 conv2)]
__device__ __align__(16) float g_wrT[64*64];    // res_w transposed [c][o]
__device__ __align__(16) float g_wkT[64*64];    // skip_w transposed [c][o]
__device__ float g_tab[Bc*Nn*24*128];  // folded const+seasonal contribution [bn][ph][oc]
__device__ float g_corr[Bc*Nn*128];    // t==0 left-pad correction [bn][oc]

// ---------------- K0: adjacency softmax -------------------------------------
__global__ void k_adj(const float* __restrict__ emb){
    int n = blockIdx.x, m = threadIdx.x;
    float d = 0.f;
    #pragma unroll
    for (int k = 0; k < 64; k++) d += emb[n*64+k]*emb[m*64+k];
    if (m == n) d -= 10.f;
    __shared__ float red[4];
    int lane = m & 31, w = m >> 5;
    float v = d;
    #pragma unroll
    for (int o = 16; o > 0; o >>= 1) v = fmaxf(v, __shfl_xor_sync(0xffffffffu, v, o));
    if (lane == 0) red[w] = v;
    __syncthreads();
    float mx = fmaxf(fmaxf(red[0],red[1]), fmaxf(red[2],red[3]));
    __syncthreads();
    float e = expf(d - mx);
    v = e;
    #pragma unroll
    for (int o = 16; o > 0; o >>= 1) v += __shfl_xor_sync(0xffffffffu, v, o);
    if (lane == 0) red[w] = v;
    __syncthreads();
    float s = red[0]+red[1]+red[2]+red[3];
    float a = e / s;
    g_adj[n*Nn + m] = a;
    g_adjT[m*Nn + n] = a;
}

// ---------------- K_w: weight reorder ----------------------------------------
__global__ void k_wprep(const float* __restrict__ c1w, const float* __restrict__ c2w,
                        const float* __restrict__ resw, const float* __restrict__ skw){
    int i = blockIdx.x*256 + threadIdx.x;
    if (i < 832*2*128) {
        int oc = i & 127, tap = (i >> 7) & 1, ic = i >> 8;
        g_wcomb[i] = (oc < 64) ? c1w[(oc*832+ic)*2 + tap]
                               : c2w[((oc-64)*832+ic)*2 + tap];
    }
    if (i < 4096) {
        int o = i >> 6, c = i & 63;
        g_wrT[c*64+o] = resw[i];
        g_wkT[c*64+o] = skw[i];
    }
}

// ---------------- K1: per-row temporal norms ---------------------------------
__global__ void k_temporal(const float* __restrict__ x){
    int row = blockIdx.x;
    int t = threadIdx.x;                       // 0..287
    __shared__ float s1[Tc], s2[Tc];
    __shared__ float rs[9], rq[9];
    __shared__ float smv[24], siv[24];
    float xv = x[row*Tc + t];
    // long-term (whole-sequence) stats
    float sum = xv, sq = xv*xv;
    #pragma unroll
    for (int o = 16; o > 0; o >>= 1) {
        sum += __shfl_down_sync(0xffffffffu, sum, o);
        sq  += __shfl_down_sync(0xffffffffu, sq,  o);
    }
    if ((t & 31) == 0) { rs[t>>5] = sum; rq[t>>5] = sq; }
    __syncthreads();
    if (t == 0) {
        float a = 0.f, b = 0.f;
        #pragma unroll
        for (int i = 0; i < 9; i++) { a += rs[i]; b += rq[i]; }
        rs[0] = a; rq[0] = b;
    }
    __syncthreads();
    float m1 = rs[0] * (1.f/Tc);
    float v1 = rq[0] * (1.f/Tc) - m1*m1 + 1e-5f;
    float x1v = (xv - m1) * rsqrtf(v1 + 0.01f);
    s1[t] = x1v;
    g_x1[row*TP + t] = x1v;
    if (t == 0) { g_ltm[row] = m1; g_lts[row] = sqrtf(v1); }
    __syncthreads();
    // seasonal (cycle 24, 12 chunks)
    if (t < 24) {
        float a = 0.f, b = 0.f;
        #pragma unroll
        for (int k = 0; k < 12; k++) { float v = s1[t + 24*k]; a += v; b += v*v; }
        float mm = a * (1.f/12.f);
        float vv = b * (1.f/12.f) - mm*mm + 1e-5f;
        smv[t] = mm;
        siv[t] = rsqrtf(vv + 0.01f);
        g_sm[row*24 + t] = mm;
        g_ss[row*24 + t] = sqrtf(vv);
    }
    __syncthreads();
    int ph = t % 24;
    float x2v = (x1v - smv[ph]) * siv[ph];
    s2[t] = x2v;
    g_x2[row*TP + t] = x2v;
    __syncthreads();
    // short-period sliding window (width 12, window ends at max(t,11))
    int te = (t < 11) ? 11 : t;
    float a = 0.f, b = 0.f;
    #pragma unroll
    for (int j = 0; j < 12; j++) { float v = s2[te-11+j]; a += v; b += v*v; }
    float mm = a * (1.f/12.f);
    float vv = b * (1.f/12.f) - mm*mm + 1e-5f;
    g_stm[row*Tc + t] = mm;
    g_sts[row*Tc + t] = sqrtf(vv);
    g_x3[row*TP + t] = (x2v - mm) * rsqrtf(vv + 0.01f);
}

// ---------------- K2: spatial norm (register-tiled, f32x2) --------------------
__global__ void __launch_bounds__(256) k_spatial(){
    int bc = blockIdx.x;            // 0..511 (b*64+c)
    int t0 = blockIdx.y * 32;
    __shared__ __align__(16) float s3[Nn*32];   // [m][t] 16KB
    int tid = threadIdx.x;          // 256
    for (int idx = tid; idx < Nn*32; idx += 256) {
        int m = idx >> 5, j = idx & 31;
        s3[idx] = g_x3[(bc*Nn + m)*TP + t0 + j];
    }
    __syncthreads();
    int tx = tid & 7, ty = tid >> 3;   // 8 t-groups x 32 n-groups
    int tb = tx*4, n0 = ty*4;
    unsigned long long a1p[2][4] = {}, a2p[2][4] = {};
    #pragma unroll 4
    for (int m = 0; m < Nn; m++) {
        float4 xv = *(const float4*)&s3[m*32 + tb];
        ulonglong2 ap = *(const ulonglong2*)&g_adjT[m*Nn + n0];
        unsigned long long xd[4] = {packdup(xv.x), packdup(xv.y),
                                    packdup(xv.z), packdup(xv.w)};
        #pragma unroll
        for (int j = 0; j < 4; j++) {
            unsigned long long xq = mul2(xd[j], xd[j]);
            fma2(a1p[0][j], ap.x, xd[j]);
            fma2(a1p[1][j], ap.y, xd[j]);
            fma2(a2p[0][j], ap.x, xq);
            fma2(a2p[1][j], ap.y, xq);
        }
    }
    #pragma unroll
    for (int ip = 0; ip < 2; ip++) {
        float mn[2][4], sq[2][4];
        #pragma unroll
        for (int j = 0; j < 4; j++) {
            unpack2(a1p[ip][j], mn[0][j], mn[1][j]);
            unpack2(a2p[ip][j], sq[0][j], sq[1][j]);
        }
        #pragma unroll
        for (int h = 0; h < 2; h++) {
            int n = n0 + ip*2 + h;
            int ro = bc*Nn + n;
            float x4o[4], mo[4], so[4];
            #pragma unroll
            for (int j = 0; j < 4; j++) {
                float mean = mn[h][j];
                float var = sq[h][j] - mean*mean + 1e-5f;
                float xv = s3[n*32 + tb + j];
                x4o[j] = (xv - mean) * rsqrtf(var + 0.01f);
                mo[j] = mean;
                so[j] = sqrtf(var);
            }
            *(float4*)&g_x4[ro*TP + t0 + tb]  = *(float4*)x4o;
            *(float4*)&g_spm[ro*Tc + t0 + tb] = *(float4*)mo;
            *(float4*)&g_sps[ro*Tc + t0 + tb] = *(float4*)so;
        }
    }
}

// ---------------- K3: residual extrapolation GEMMs ---------------------------
__global__ void __launch_bounds__(256) k_extrap(
        const float* __restrict__ w1, const float* __restrict__ b1,
        const float* __restrict__ w2, const float* __restrict__ b2,
        const float* __restrict__ w3, const float* __restrict__ b3,
        const float* __restrict__ w4, const float* __restrict__ b4){
    int which = blockIdx.z >> 3;
    int b = blockIdx.z & 7;
    int o0 = blockIdx.x * 64;
    int n0 = blockIdx.y * 32;
    const float* wt; const float* bs; float* xio;
    if (which == 0)      { wt = w1; bs = b1; xio = g_x1; }
    else if (which == 1) { wt = w2; bs = b2; xio = g_x2; }
    else if (which == 2) { wt = w3; bs = b3; xio = g_x3; }
    else                 { wt = w4; bs = b4; xio = g_x4; }

    __shared__ __align__(16) float Vs[64*32];
    __shared__ float Ws[64*64];
    int tid = threadIdx.x;
    int tx = tid & 7;          // 4 n each
    int ty = tid >> 3;         // o = o0+ty and o0+ty+32
    float acc0[4] = {0,0,0,0}, acc1[4] = {0,0,0,0};
    for (int kt = 0; kt < 12; kt++) {
        __syncthreads();
        for (int idx = tid; idx < 2048; idx += 256) {
            int k = idx >> 5, nn = idx & 31;
            int kk = kt*64 + k;
            int c = kk / 12, l = kk - c*12;
            Vs[idx] = xio[((b*Cc + c)*Nn + n0 + nn)*TP + 276 + l];
        }
        for (int idx = tid; idx < 4096; idx += 256) {
            int k = idx >> 6, oc = idx & 63;
            Ws[idx] = wt[(o0 + oc)*768 + kt*64 + k];
        }
        __syncthreads();
        #pragma unroll 8
        for (int k = 0; k < 64; k++) {
            float w0 = Ws[k*64 + ty];
            float wA = Ws[k*64 + 32 + ty];
            float4 vv = *(const float4*)&Vs[k*32 + tx*4];
            float v[4] = {vv.x, vv.y, vv.z, vv.w};
            #pragma unroll
            for (int j = 0; j < 4; j++) {
                acc0[j] = fmaf(w0, v[j], acc0[j]);
                acc1[j] = fmaf(wA, v[j], acc1[j]);
            }
        }
    }
    int o = o0 + ty;
    float bv = bs[o];
    int p = o >> 6, c2 = o & 63;
    #pragma unroll
    for (int j = 0; j < 4; j++)
        xio[((b*Cc + c2)*Nn + n0 + tx*4 + j)*TP + Tc + p] = acc0[j] + bv;
    o = o0 + ty + 32;
    bv = bs[o]; p = o >> 6; c2 = o & 63;
    #pragma unroll
    for (int j = 0; j < 4; j++)
        xio[((b*Cc + c2)*Nn + n0 + tx*4 + j)*TP + Tc + p] = acc1[j] + bv;
}

// ---------------- K_tab: fold constant + periodic xcat groups ----------------
__global__ void __launch_bounds__(128) k_tab(){
    int bn = blockIdx.x;            // b*128 + n
    int b = bn >> 7, n = bn & 127;
    __shared__ float s_sm[64*24], s_ss[64*24], s_ltm[64], s_lts[64];
    int tid = threadIdx.x;
    for (int idx = tid; idx < 1536; idx += 128) {
        int c = idx / 24, ph = idx - c*24;
        int row = (b*Cc + c)*Nn + n;
        s_sm[idx] = g_sm[row*24 + ph];
        s_ss[idx] = g_ss[row*24 + ph];
    }
    if (tid < 64) {
        int row = (b*Cc + tid)*Nn + n;
        s_ltm[tid] = g_ltm[row];
        s_lts[tid] = g_lts[row];
    }
    __syncthreads();
    int oc = tid;                   // 0..127
    float tab[24];
    #pragma unroll
    for (int p = 0; p < 24; p++) tab[p] = 0.f;
    float corr = 0.f, base = 0.f;
    for (int c = 0; c < 64; c++) {
        float w2t0 = g_wcomb[((128+c)*2+0)*128+oc];
        float w2t1 = g_wcomb[((128+c)*2+1)*128+oc];
        float w3t0 = g_wcomb[((192+c)*2+0)*128+oc];
        float w3t1 = g_wcomb[((192+c)*2+1)*128+oc];
        base += (w2t0+w2t1)*s_ltm[c] + (w3t0+w3t1)*s_lts[c];
        corr += w2t0*s_ltm[c] + w3t0*s_lts[c];
        float w5t0 = g_wcomb[((320+c)*2+0)*128+oc];
        float w5t1 = g_wcomb[((320+c)*2+1)*128+oc];
        float w6t0 = g_wcomb[((384+c)*2+0)*128+oc];
        float w6t1 = g_wcomb[((384+c)*2+1)*128+oc];
        const float* smc = &s_sm[c*24];
        const float* ssc = &s_ss[c*24];
        corr += w5t0*smc[23] + w6t0*ssc[23];
        #pragma unroll
        for (int p = 0; p < 24; p++) {
            int pm = (p + 23) % 24;   // phase of t-1
            tab[p] = fmaf(w5t0, smc[pm], tab[p]);
            tab[p] = fmaf(w5t1, smc[p],  tab[p]);
            tab[p] = fmaf(w6t0, ssc[pm], tab[p]);
            tab[p] = fmaf(w6t1, ssc[p],  tab[p]);
        }
    }
    #pragma unroll
    for (int p = 0; p < 24; p++)
        g_tab[(bn*24 + p)*128 + oc] = tab[p] + base;
    g_corr[bn*128 + oc] = corr;
}

// ---------------- K4: fused gated conv + output 1x1s (f32x2) -----------------
__device__ __forceinline__ float gather_xcat(const float* __restrict__ x,
                                             int b, int ch, int n, int t){
    int g = ch >> 6, c = ch & 63;
    int row = (b*Cc + c)*Nn + n;
    int tc = (t < Tc) ? t : (Tc - 1);
    switch (g) {
        case 0:  return x[row*Tc + tc];
        case 1:  return g_x1[row*TP + t];
        case 4:  return g_x2[row*TP + t];
        case 7:  return g_x3[row*TP + t];
        case 8:  return g_stm[row*Tc + tc];
        case 9:  return g_sts[row*Tc + tc];
        case 10: return g_x4[row*TP + t];
        case 11: return g_spm[row*Tc + tc];
        default: return g_sps[row*Tc + tc];   // 12
    }
}

__global__ void __launch_bounds__(256) k_convout(const float* __restrict__ x,
        const float* __restrict__ c1b, const float* __restrict__ c2b,
        const float* __restrict__ resb, const float* __restrict__ skb,
        float* __restrict__ out){
    int t0 = blockIdx.x * 64;
    int n  = blockIdx.y;
    int b  = blockIdx.z;
    int bn = b*Nn + n;
    __shared__ __align__(16) float xs[16*68];
    __shared__ __align__(16) float wz[64*68];   // weights (4096 floats) in loop, z after
    __shared__ float tabs[24*128];
    __shared__ float corrs[128];
    int tid = threadIdx.x;
    for (int idx = tid; idx < 3072; idx += 256) tabs[idx] = g_tab[bn*3072 + idx];
    if (tid < 128) corrs[tid] = g_corr[bn*128 + tid];
    int ocg = tid & 15;   // c base = ocg*4
    int tg  = tid >> 4;   // t base = tg*4
    unsigned long long acc1[2][4] = {}, acc2[2][4] = {};   // [oc-pair][t]
    for (int kti = 0; kti < 36; kti++) {
        // skip kt in {8..15} (const groups 2,3) and {20..27} (seasonal 5,6)
        int kt = (kti < 8) ? kti : ((kti < 12) ? kti + 8 : kti + 16);
        __syncthreads();
        for (int idx = tid; idx < 16*65; idx += 256) {
            int icl = idx / 65, j = idx - icl*65;
            int t = t0 - 1 + j;
            float v = 0.f;
            if (t >= 0 && t < TP) v = gather_xcat(x, b, kt*16 + icl, n, t);
            xs[icl*68 + j] = v;
        }
        for (int idx = tid; idx < 4096; idx += 256)
            wz[idx] = g_wcomb[kt*4096 + idx];
        __syncthreads();
        #pragma unroll
        for (int ic = 0; ic < 16; ic++) {
            float4 xv4 = *(const float4*)&xs[ic*68 + tg*4];
            float xv5 = xs[ic*68 + tg*4 + 4];
            unsigned long long xd[5] = {packdup(xv4.x), packdup(xv4.y),
                                        packdup(xv4.z), packdup(xv4.w), packdup(xv5)};
            #pragma unroll
            for (int tap = 0; tap < 2; tap++) {
                ulonglong2 wA = *(const ulonglong2*)&wz[(ic*2+tap)*128 + ocg*4];
                ulonglong2 wB = *(const ulonglong2*)&wz[(ic*2+tap)*128 + 64 + ocg*4];
                #pragma unroll
                for (int j = 0; j < 4; j++) {
                    fma2(acc1[0][j], wA.x, xd[j+tap]);
                    fma2(acc1[1][j], wA.y, xd[j+tap]);
                    fma2(acc2[0][j], wB.x, xd[j+tap]);
                    fma2(acc2[1][j], wB.y, xd[j+tap]);
                }
            }
        }
    }
    // unpack packed accumulators -> f1[i][j], f2[i][j]  (i = oc local 0..3)
    float f1[4][4], f2[4][4];
    #pragma unroll
    for (int ip = 0; ip < 2; ip++)
        #pragma unroll
        for (int j = 0; j < 4; j++) {
            unpack2(acc1[ip][j], f1[ip*2][j], f1[ip*2+1][j]);
            unpack2(acc2[ip][j], f2[ip*2][j], f2[ip*2+1][j]);
        }
    __syncthreads();   // done reading wz as weights
    // gating epilogue: z -> wz (reused as [c][t_local] with stride 68)
    #pragma unroll
    for (int i = 0; i < 4; i++) {
        int c = ocg*4 + i;
        float bb1 = c1b[c], bb2 = c2b[c];
        #pragma unroll
        for (int j = 0; j < 4; j++) {
            int lt = tg*4 + j;
            int t = t0 + lt;
            int ph = t % 24;
            float a1 = f1[i][j] + tabs[ph*128 + c]      + bb1;
            float a2 = f2[i][j] + tabs[ph*128 + 64 + c] + bb2;
            if (t == 0) { a1 -= corrs[c]; a2 -= corrs[64 + c]; }
            float zg = tanhf(a1) * (1.f / (1.f + expf(-a2)));
            wz[c*68 + lt] = zg;
        }
    }
    __syncthreads();
    // output 1x1 convs on z (f32x2)
    int tb = tg*4;
    const float* wsel = (t0 + tb >= Tc) ? g_wkT : g_wrT;
    unsigned long long ao[2][4] = {};
    #pragma unroll 4
    for (int k = 0; k < 64; k++) {
        float4 zv = *(const float4*)&wz[k*68 + tb];
        ulonglong2 wp = *(const ulonglong2*)&wsel[k*64 + ocg*4];
        unsigned long long zd[4] = {packdup(zv.x), packdup(zv.y),
                                    packdup(zv.z), packdup(zv.w)};
        #pragma unroll
        for (int j = 0; j < 4; j++) {
            fma2(ao[0][j], wp.x, zd[j]);
            fma2(ao[1][j], wp.y, zd[j]);
        }
    }
    float acc[4][4];
    #pragma unroll
    for (int ip = 0; ip < 2; ip++)
        #pragma unroll
        for (int j = 0; j < 4; j++)
            unpack2(ao[ip][j], acc[ip*2][j], acc[ip*2+1][j]);
    const size_t SZ1 = (size_t)Bc*Cc*Nn*Tc;
    #pragma unroll
    for (int i = 0; i < 4; i++) {
        int oc = ocg*4 + i;
        float br = resb[oc], bk = skb[oc];
        #pragma unroll
        for (int j = 0; j < 4; j++) {
            int t = t0 + tb + j;
            if (t < Tc)
                out[((size_t)(b*Cc + oc)*Nn + n)*Tc + t] = acc[i][j] + br;
            else if (t < TP)
                out[SZ1 + ((size_t)(b*Cc + oc)*Nn + n)*PRED + (t - Tc)] = acc[i][j] + bk;
        }
    }
}

// ---------------- launcher ----------------------------------------------------
extern "C" void kernel_launch(void* const* d_in, const int* in_sizes, int n_in,
                              void* d_out, int out_size){
    const float* x    = (const float*)d_in[0];
    const float* emb  = (const float*)d_in[1];
    const float* re1w = (const float*)d_in[2];  const float* re1b = (const float*)d_in[3];
    const float* re2w = (const float*)d_in[4];  const float* re2b = (const float*)d_in[5];
    const float* re3w = (const float*)d_in[6];  const float* re3b = (const float*)d_in[7];
    const float* re4w = (const float*)d_in[8];  const float* re4b = (const float*)d_in[9];
    const float* c1w  = (const float*)d_in[10]; const float* c1b  = (const float*)d_in[11];
    const float* c2w  = (const float*)d_in[12]; const float* c2b  = (const float*)d_in[13];
    const float* skw  = (const float*)d_in[14]; const float* skb  = (const float*)d_in[15];
    const float* resw = (const float*)d_in[16]; const float* resb = (const float*)d_in[17];

    k_adj<<<128, 128>>>(emb);
    k_wprep<<<(832*2*128 + 255)/256, 256>>>(c1w, c2w, resw, skw);
    k_temporal<<<ROWS, Tc>>>(x);
    k_spatial<<<dim3(512, 9, 1), 256>>>();
    k_extrap<<<dim3(12, 4, 32), 256>>>(re1w, re1b, re2w, re2b, re3w, re3b, re4w, re4b);
    k_tab<<<Bc*Nn, 128>>>();
    k_convout<<<dim3(5, 128, 8), 256>>>(x, c1b, c2b, resb, skb, (float*)d_out);
}